// round 1
// baseline (speedup 1.0000x reference)
#include <cuda_runtime.h>

// Problem constants (GCN: N=100000 nodes, E=1600000 edges, 16->64->128->16)
static constexpr int MAXN = 100000;
static constexpr int MAXE = 1600000;

// Scratch (device globals; no allocation allowed)
__device__ int   g_deg[MAXN];
__device__ float g_dinv[MAXN];
__device__ int   g_off[MAXN + 1];
__device__ int   g_cur[MAXN];
__device__ int   g_csr[MAXE];
__device__ int   g_bsum[128];
__device__ float g_xs[MAXN * 16];            // dinv-scaled input features
__device__ float g_a1[MAXN * 16];            // aggregated x
__device__ float g_h1s[(size_t)MAXN * 64];   // dinv * relu(a1@W1+b1)
__device__ float g_a2[(size_t)MAXN * 64];    // aggregated h1s
__device__ float g_w2l[64 * 16];             // W2 @ WL
__device__ float g_b2l[16];                  // b2 @ WL + bL

// ---------------------------------------------------------------- degree
__global__ void k_init_deg(int n) {
    int i = blockIdx.x * blockDim.x + threadIdx.x;
    if (i < n) g_deg[i] = 1;  // self-loop
}

__global__ void k_count(const int* __restrict__ ei, int e) {
    int i = blockIdx.x * blockDim.x + threadIdx.x;
    if (i < e) atomicAdd(&g_deg[ei[e + i]], 1);
}

__global__ void k_dinv_xs(const float* __restrict__ x, int n) {
    int i = blockIdx.x * blockDim.x + threadIdx.x;
    if (i >= n) return;
    float d = rsqrtf((float)g_deg[i]);
    g_dinv[i] = d;
    const float4* xr = (const float4*)(x + (size_t)i * 16);
    float4* o = (float4*)(g_xs + (size_t)i * 16);
#pragma unroll
    for (int r = 0; r < 4; r++) {
        float4 v = __ldg(&xr[r]);
        v.x *= d; v.y *= d; v.z *= d; v.w *= d;
        o[r] = v;
    }
}

// ---------------------------------------------------------------- CSR build (2-level scan)
__global__ void k_scan1(int n) {
    __shared__ int s[1024];
    int t = threadIdx.x, i = blockIdx.x * 1024 + t;
    int v = (i < n) ? (g_deg[i] - 1) : 0;   // edge count only (no self-loop)
    s[t] = v;
    __syncthreads();
    for (int o = 1; o < 1024; o <<= 1) {
        int a = (t >= o) ? s[t - o] : 0;
        __syncthreads();
        s[t] += a;
        __syncthreads();
    }
    if (i < n) g_off[i] = s[t] - v;  // exclusive within block
    if (t == 1023) g_bsum[blockIdx.x] = s[1023];
}

__global__ void k_scan2(int nb) {
    __shared__ int s[128];
    int t = threadIdx.x;
    int v = (t < nb) ? g_bsum[t] : 0;
    s[t] = v;
    __syncthreads();
    for (int o = 1; o < 128; o <<= 1) {
        int a = (t >= o) ? s[t - o] : 0;
        __syncthreads();
        s[t] += a;
        __syncthreads();
    }
    if (t < nb) g_bsum[t] = s[t] - v;  // exclusive
}

__global__ void k_scan3(int n, int e) {
    int t = threadIdx.x, i = blockIdx.x * 1024 + t;
    if (i < n) {
        int o = g_off[i] + g_bsum[blockIdx.x];
        g_off[i] = o;
        g_cur[i] = o;
    }
    if (i == 0) g_off[n] = e;
}

__global__ void k_fill(const int* __restrict__ ei, int e) {
    int i = blockIdx.x * blockDim.x + threadIdx.x;
    if (i >= e) return;
    int s = ei[i];
    int d = ei[e + i];
    int pos = atomicAdd(&g_cur[d], 1);
    g_csr[pos] = s;
}

// ---------------------------------------------------------------- aggregation 1 (16 floats/node)
// 4 lanes per node, each lane holds one float4.
__global__ void k_agg1(int n) {
    int tid = blockIdx.x * blockDim.x + threadIdx.x;
    int node = tid >> 2;
    if (node >= n) return;
    int j = tid & 3;
    int st = g_off[node], en = g_off[node + 1];
    const float4* xs4 = (const float4*)g_xs;
    float4 acc = __ldg(&xs4[node * 4 + j]);  // self term (already dinv-scaled)
    float4 acc2 = make_float4(0.f, 0.f, 0.f, 0.f);
    int e = st;
    for (; e + 1 < en; e += 2) {
        int s0 = __ldg(&g_csr[e]);
        int s1 = __ldg(&g_csr[e + 1]);
        float4 v0 = __ldg(&xs4[s0 * 4 + j]);
        float4 v1 = __ldg(&xs4[s1 * 4 + j]);
        acc.x += v0.x; acc.y += v0.y; acc.z += v0.z; acc.w += v0.w;
        acc2.x += v1.x; acc2.y += v1.y; acc2.z += v1.z; acc2.w += v1.w;
    }
    if (e < en) {
        int s0 = __ldg(&g_csr[e]);
        float4 v0 = __ldg(&xs4[s0 * 4 + j]);
        acc.x += v0.x; acc.y += v0.y; acc.z += v0.z; acc.w += v0.w;
    }
    float d = __ldg(&g_dinv[node]);
    float4 r;
    r.x = d * (acc.x + acc2.x);
    r.y = d * (acc.y + acc2.y);
    r.z = d * (acc.z + acc2.z);
    r.w = d * (acc.w + acc2.w);
    ((float4*)g_a1)[node * 4 + j] = r;
}

// ---------------------------------------------------------------- GEMM1: h1s = dinv * relu(a1 @ W1 + b1)
// 256 threads, 64 nodes/block, 4 threads per node (16 cols each).
__global__ void k_gemm1(const float* __restrict__ W1, const float* __restrict__ b1, int n) {
    __shared__ float4 w4[16 * 16];  // W1 [16][64] as [k][c4]
    __shared__ float a_s[64 * 17];
    __shared__ float b_s[64];
    int t = threadIdx.x;
    w4[t] = __ldg(&((const float4*)W1)[t]);
    if (t < 64) b_s[t] = __ldg(&b1[t]);
    int nb = blockIdx.x * 64;
#pragma unroll
    for (int r = 0; r < 4; r++) {
        int i = t + r * 256;
        int node = nb + (i >> 4);
        float v = (node < n) ? g_a1[(size_t)nb * 16 + i] : 0.f;
        a_s[(i >> 4) * 17 + (i & 15)] = v;
    }
    __syncthreads();
    int nl = t >> 2, q = t & 3;
    int node = nb + nl;
    if (node >= n) return;
    float a[16];
#pragma unroll
    for (int k = 0; k < 16; k++) a[k] = a_s[nl * 17 + k];
    float4 acc[4];
#pragma unroll
    for (int j = 0; j < 4; j++) {
        int c = q * 16 + j * 4;
        acc[j] = make_float4(b_s[c], b_s[c + 1], b_s[c + 2], b_s[c + 3]);
    }
#pragma unroll
    for (int k = 0; k < 16; k++) {
        float av = a[k];
#pragma unroll
        for (int j = 0; j < 4; j++) {
            float4 w = w4[k * 16 + q * 4 + j];
            acc[j].x += av * w.x; acc[j].y += av * w.y;
            acc[j].z += av * w.z; acc[j].w += av * w.w;
        }
    }
    float d = g_dinv[node];
    float4* out = (float4*)(g_h1s + (size_t)node * 64);
#pragma unroll
    for (int j = 0; j < 4; j++) {
        float4 v = acc[j];
        v.x = d * fmaxf(v.x, 0.f);
        v.y = d * fmaxf(v.y, 0.f);
        v.z = d * fmaxf(v.z, 0.f);
        v.w = d * fmaxf(v.w, 0.f);
        out[q * 4 + j] = v;
    }
}

// ---------------------------------------------------------------- aggregation 2 (64 floats/node)
// One warp per node; each lane accumulates a float2 (cols 2*lane, 2*lane+1).
__global__ void k_agg2(int n) {
    int warp = (blockIdx.x * blockDim.x + threadIdx.x) >> 5;
    int lane = threadIdx.x & 31;
    if (warp >= n) return;
    int node = warp;
    int st = g_off[node], en = g_off[node + 1];
    const float2* h2 = (const float2*)g_h1s;
    float2 self = __ldg(&h2[(size_t)node * 32 + lane]);
    float ax = self.x, ay = self.y, bx = 0.f, by = 0.f;
    int e = st;
    for (; e + 1 < en; e += 2) {
        int s0 = __ldg(&g_csr[e]);
        int s1 = __ldg(&g_csr[e + 1]);
        float2 v0 = __ldg(&h2[(size_t)s0 * 32 + lane]);
        float2 v1 = __ldg(&h2[(size_t)s1 * 32 + lane]);
        ax += v0.x; ay += v0.y;
        bx += v1.x; by += v1.y;
    }
    if (e < en) {
        int s0 = __ldg(&g_csr[e]);
        float2 v0 = __ldg(&h2[(size_t)s0 * 32 + lane]);
        ax += v0.x; ay += v0.y;
    }
    float d = __ldg(&g_dinv[node]);
    float2 r;
    r.x = d * (ax + bx);
    r.y = d * (ay + by);
    ((float2*)g_a2)[(size_t)node * 32 + lane] = r;
}

// ---------------------------------------------------------------- fold trailing linears: W2L = W2@WL, b2L = b2@WL + bL
__global__ void k_w2l(const float* __restrict__ W2, const float* __restrict__ b2,
                      const float* __restrict__ WL, const float* __restrict__ bL) {
    int t = threadIdx.x;  // 1024 threads
    int k = t >> 4, c = t & 15;
    float s = 0.f;
    for (int j = 0; j < 128; j++)
        s += __ldg(&W2[k * 128 + j]) * __ldg(&WL[j * 16 + c]);
    g_w2l[t] = s;
    if (t < 16) {
        float sb = __ldg(&bL[t]);
        for (int j = 0; j < 128; j++)
            sb += __ldg(&b2[j]) * __ldg(&WL[j * 16 + t]);
        g_b2l[t] = sb;
    }
}

// ---------------------------------------------------------------- GEMM2: out = a2 @ W2L + b2L
__global__ void k_gemm2(float* __restrict__ out, int n) {
    __shared__ float4 w4[64 * 4];   // W2L [64][16] as [k][c4]
    __shared__ float a_s[64 * 65];
    __shared__ float b_s[16];
    int t = threadIdx.x;
    w4[t] = ((const float4*)g_w2l)[t];
    if (t < 16) b_s[t] = g_b2l[t];
    int nb = blockIdx.x * 64;
#pragma unroll
    for (int r = 0; r < 16; r++) {
        int i = t + r * 256;
        int node = nb + (i >> 6);
        float v = (node < n) ? g_a2[(size_t)nb * 64 + i] : 0.f;
        a_s[(i >> 6) * 65 + (i & 63)] = v;
    }
    __syncthreads();
    int nl = t >> 2, q = t & 3;
    int node = nb + nl;
    if (node >= n) return;
    float4 acc = make_float4(b_s[q * 4], b_s[q * 4 + 1], b_s[q * 4 + 2], b_s[q * 4 + 3]);
#pragma unroll
    for (int k = 0; k < 64; k++) {
        float av = a_s[nl * 65 + k];
        float4 w = w4[k * 4 + q];
        acc.x += av * w.x; acc.y += av * w.y;
        acc.z += av * w.z; acc.w += av * w.w;
    }
    ((float4*)out)[(size_t)node * 4 + q] = acc;
}

// ----------------------------------------------------------------
extern "C" void kernel_launch(void* const* d_in, const int* in_sizes, int n_in,
                              void* d_out, int out_size) {
    const float* x  = (const float*)d_in[0];
    const int*   ei = (const int*)d_in[1];
    const float* W1 = (const float*)d_in[2];
    const float* b1 = (const float*)d_in[3];
    const float* W2 = (const float*)d_in[4];
    const float* b2 = (const float*)d_in[5];
    const float* WL = (const float*)d_in[6];
    const float* bL = (const float*)d_in[7];
    float* out = (float*)d_out;

    int n = in_sizes[0] / 16;   // 100000
    int e = in_sizes[1] / 2;    // 1600000
    int nb1024 = (n + 1023) / 1024;

    k_w2l<<<1, 1024>>>(W2, b2, WL, bL);
    k_init_deg<<<(n + 255) / 256, 256>>>(n);
    k_count<<<(e + 255) / 256, 256>>>(ei, e);
    k_dinv_xs<<<(n + 255) / 256, 256>>>(x, n);
    k_scan1<<<nb1024, 1024>>>(n);
    k_scan2<<<1, 128>>>(nb1024);
    k_scan3<<<nb1024, 1024>>>(n, e);
    k_fill<<<(e + 255) / 256, 256>>>(ei, e);
    k_agg1<<<(n * 4 + 255) / 256, 256>>>(n);
    k_gemm1<<<(n + 63) / 64, 256>>>(W1, b1, n);
    k_agg2<<<(n + 7) / 8, 256>>>(n);
    k_gemm2<<<(n + 63) / 64, 256>>>(out, n);
}